// round 9
// baseline (speedup 1.0000x reference)
#include <cuda_runtime.h>
#include <cuda_fp16.h>
#include <mma.h>

using namespace nvcuda;

#define S 128
#define H 64
#define LDH 72     // leading dim for half tiles (144 B = 9*16, LDSM conflict-free)
#define LDF 68     // leading dim for float h2 rows (272 B = 17*16, conflict-free float4)
#define RPB 2      // rays per block
#define NT  256    // threads per block (RPB * 128)

// Dynamic shared memory layout (bytes):
//   [0, 36864)       h1_hi half[256*LDH]
//   [36864, 73728)   h1_lo half[256*LDH]
//   (alias) [0, 69632)  h2 float[256*LDF]   -- overlaps h1 pair
//   [73728, 82944)   W2_hi half[64*LDH]  (copied pre-packed from global)
//   [82944, 92160)   W2_lo half[64*LDH]
//   [92160, 92192)   sWprod float[8]
//   [92192, 92288)   sSum  float[8][3]
#define SMEM_BYTES 92288

// Pre-split W2 (Markidis hi/lo fp16) in the FINAL padded smem layout,
// packed once per launch. __device__ globals are zero-initialized, so the
// LDH padding columns stay zero.
__device__ __align__(16) __half gW2hi[H * LDH];
__device__ __align__(16) __half gW2lo[H * LDH];

__global__ void pack_w2_kernel(const float* __restrict__ W2)
{
    const int i = blockIdx.x * blockDim.x + threadIdx.x;
    if (i < H * H) {
        const int k = i >> 6, j = i & 63;
        const float w = W2[i];
        const __half hi = __float2half_rn(w);
        gW2hi[k * LDH + j] = hi;
        gW2lo[k * LDH + j] = __float2half_rn(w - __half2float(hi));
    }
}

__global__ __launch_bounds__(NT, 2)
void render_kernel(const float* __restrict__ rays_o,
                   const float* __restrict__ rays_d,
                   const float* __restrict__ nearv,
                   const float* __restrict__ farv,
                   const float* __restrict__ jitter,
                   const float* __restrict__ density,
                   const float* __restrict__ W1,
                   const float* __restrict__ b1,
                   const float* __restrict__ b2,
                   const float* __restrict__ Wsig,
                   const float* __restrict__ bsig,
                   const float* __restrict__ Wrgb,
                   const float* __restrict__ brgb,
                   float* __restrict__ out)
{
    extern __shared__ __align__(16) char smem[];
    __half* hH1hi = reinterpret_cast<__half*>(smem);
    __half* hH1lo = reinterpret_cast<__half*>(smem + 36864);
    float*  fH2   = reinterpret_cast<float*>(smem);            // aliases h1 pair
    __half* sW2hi = reinterpret_cast<__half*>(smem + 73728);
    __half* sW2lo = reinterpret_cast<__half*>(smem + 82944);
    float*  sWprod = reinterpret_cast<float*>(smem + 92160);   // [8]
    float*  sSum   = reinterpret_cast<float*>(smem + 92192);   // [8][3]

    const int t        = threadIdx.x;       // 0..255
    const int lane     = t & 31;
    const int warp     = t >> 5;            // 0..7
    const int rayLocal = warp >> 2;         // 0 or 1
    const int warpInRay = warp & 3;
    const int samp     = t & 127;           // sample index within ray
    const int ray      = blockIdx.x * RPB + rayLocal;

    // ---- per-sample ray setup + occupancy-grid mask ----
    const float ox = rays_o[ray * 3 + 0];
    const float oy = rays_o[ray * 3 + 1];
    const float oz = rays_o[ray * 3 + 2];
    const float dx = rays_d[ray * 3 + 0];
    const float dy = rays_d[ray * 3 + 1];
    const float dz = rays_d[ray * 3 + 2];
    const float nr = nearv[ray];
    const float fr = farv[ray];
    const float step = (fr - nr) * (1.0f / (float)S);
    const float z = nr + (float)samp * step;

    const float p0x = ox + z * dx;
    const float p0y = oy + z * dy;
    const float p0z = oz + z * dz;
    const float ux = (p0x - (-1.25f)) / 2.5f;
    const float uy = (p0y - (-1.55f)) / 2.5f;
    const float uz = (p0z - (-1.25f)) / 2.5f;
    const int ix = (int)floorf(ux * 64.0f);
    const int iy = (int)floorf(uy * 64.0f);
    const int iz = (int)floorf(uz * 64.0f);
    const bool inb = (ix >= 0) & (ix < 64) & (iy >= 0) & (iy < 64) & (iz >= 0) & (iz < 64);
    const int cx = min(max(ix, 0), 63);
    const int cy = min(max(iy, 0), 63);
    const int cz = min(max(iz, 0), 63);
    const bool occ = density[(cx * 64 + cy) * 64 + cz] > 0.5f;
    const bool mask = occ && inb;

    // Both rays fully empty? -> exact white for both.
    const int any_active = __syncthreads_or(mask ? 1 : 0);
    if (!any_active) {
        if (samp == 0) {
            out[ray * 3 + 0] = 1.0f;
            out[ray * 3 + 1] = 1.0f;
            out[ray * 3 + 2] = 1.0f;
        }
        return;
    }

    // ---- copy pre-packed W2 hi/lo into shared (pure int4 memcpy) ----
    {
        const int4* src_hi = reinterpret_cast<const int4*>(gW2hi);
        const int4* src_lo = reinterpret_cast<const int4*>(gW2lo);
        int4* dst_hi = reinterpret_cast<int4*>(sW2hi);
        int4* dst_lo = reinterpret_cast<int4*>(sW2lo);
        #pragma unroll
        for (int i = t; i < (H * LDH) / 8; i += NT) {   // 576 int4 each
            dst_hi[i] = src_hi[i];
            dst_lo[i] = src_lo[i];
        }
    }

    // Warp-level skip: all-culled warps never have their MLP rows read.
    const unsigned wball = __ballot_sync(0xffffffffu, mask);
    const bool warp_active = (wball != 0u);

    const float zv = mask ? z : 0.0f;
    const float zj = zv + jitter[ray * S + samp] * step;
    const float px = ox + zj * dx;
    const float py = oy + zj * dy;
    const float pz = oz + zj * dz;

    // ---- layer 1 (scalar fp32, K=3): vectorized 128-bit h1 stores ----
    if (warp_active) {
        uint4* hrowHi = reinterpret_cast<uint4*>(hH1hi + t * LDH);
        uint4* hrowLo = reinterpret_cast<uint4*>(hH1lo + t * LDH);
        #pragma unroll
        for (int j8 = 0; j8 < H; j8 += 8) {
            uint4 vhi, vlo;
            __half2* phi = reinterpret_cast<__half2*>(&vhi);
            __half2* plo = reinterpret_cast<__half2*>(&vlo);
            #pragma unroll
            for (int u = 0; u < 4; u++) {
                const int j = j8 + u * 2;
                float v0 = b1[j];
                v0 = fmaf(px, W1[j], v0);
                v0 = fmaf(py, W1[H + j], v0);
                v0 = fmaf(pz, W1[2 * H + j], v0);
                v0 = fmaxf(v0, 0.0f);
                float v1 = b1[j + 1];
                v1 = fmaf(px, W1[j + 1], v1);
                v1 = fmaf(py, W1[H + j + 1], v1);
                v1 = fmaf(pz, W1[2 * H + j + 1], v1);
                v1 = fmaxf(v1, 0.0f);
                const __half h0 = __float2half_rn(v0);
                const __half h1 = __float2half_rn(v1);
                const __half l0 = __float2half_rn(v0 - __half2float(h0));
                const __half l1 = __float2half_rn(v1 - __half2float(h1));
                phi[u] = __halves2half2(h0, h1);
                plo[u] = __halves2half2(l0, l1);
            }
            hrowHi[j8 >> 3] = vhi;
            hrowLo[j8 >> 3] = vlo;
        }
    }
    __syncthreads();   // h1 rows + W2 smem copy visible to all warps

    // ---- layer 2: h2 = h_hi*w_hi + h_hi*w_lo + h_lo*w_hi (fp32 accum) ----
    wmma::fragment<wmma::accumulator, 16, 16, 16, float> c[2][4];
    if (warp_active) {
        #pragma unroll
        for (int mt = 0; mt < 2; mt++)
            #pragma unroll
            for (int nt = 0; nt < 4; nt++)
                wmma::fill_fragment(c[mt][nt], 0.0f);

        #pragma unroll
        for (int k = 0; k < 4; k++) {
            wmma::fragment<wmma::matrix_a, 16, 16, 16, __half, wmma::row_major> aHi0, aHi1, aLo0, aLo1;
            wmma::load_matrix_sync(aHi0, hH1hi + (warp * 32) * LDH + k * 16, LDH);
            wmma::load_matrix_sync(aHi1, hH1hi + (warp * 32 + 16) * LDH + k * 16, LDH);
            wmma::load_matrix_sync(aLo0, hH1lo + (warp * 32) * LDH + k * 16, LDH);
            wmma::load_matrix_sync(aLo1, hH1lo + (warp * 32 + 16) * LDH + k * 16, LDH);
            #pragma unroll
            for (int nt = 0; nt < 4; nt++) {
                wmma::fragment<wmma::matrix_b, 16, 16, 16, __half, wmma::row_major> bHi, bLo;
                wmma::load_matrix_sync(bHi, sW2hi + (k * 16) * LDH + nt * 16, LDH);
                wmma::load_matrix_sync(bLo, sW2lo + (k * 16) * LDH + nt * 16, LDH);
                wmma::mma_sync(c[0][nt], aHi0, bHi, c[0][nt]);
                wmma::mma_sync(c[1][nt], aHi1, bHi, c[1][nt]);
                wmma::mma_sync(c[0][nt], aHi0, bLo, c[0][nt]);
                wmma::mma_sync(c[1][nt], aHi1, bLo, c[1][nt]);
                wmma::mma_sync(c[0][nt], aLo0, bHi, c[0][nt]);
                wmma::mma_sync(c[1][nt], aLo1, bHi, c[1][nt]);
            }
        }
    }

    // fH2 aliases the h1 buffers: all MMA reads must finish before stores.
    __syncthreads();
    if (warp_active) {
        #pragma unroll
        for (int mt = 0; mt < 2; mt++)
            #pragma unroll
            for (int nt = 0; nt < 4; nt++)
                wmma::store_matrix_sync(fH2 + (warp * 32 + mt * 16) * LDF + nt * 16,
                                        c[mt][nt], LDF, wmma::mem_row_major);
    }
    __syncthreads();

    // ---- heads (scalar fp32), only for active samples; weights via uniform LDG ----
    float alpha = 0.0f, r = 0.0f, g = 0.0f, b = 0.0f;
    if (mask) {
        float sigma = bsig[0];
        float cr = brgb[0], cg = brgb[1], cb = brgb[2];
        const float4* hrow = reinterpret_cast<const float4*>(fH2 + t * LDF);
        #pragma unroll
        for (int jq = 0; jq < 16; jq++) {
            const float4 hv = hrow[jq];
            const int j = jq * 4;
            const float h0 = fmaxf(hv.x + b2[j + 0], 0.0f);
            const float h1 = fmaxf(hv.y + b2[j + 1], 0.0f);
            const float h2 = fmaxf(hv.z + b2[j + 2], 0.0f);
            const float h3 = fmaxf(hv.w + b2[j + 3], 0.0f);
            sigma = fmaf(h0, Wsig[j + 0], sigma);
            sigma = fmaf(h1, Wsig[j + 1], sigma);
            sigma = fmaf(h2, Wsig[j + 2], sigma);
            sigma = fmaf(h3, Wsig[j + 3], sigma);
            cr = fmaf(h0, Wrgb[(j + 0) * 3 + 0], cr);
            cg = fmaf(h0, Wrgb[(j + 0) * 3 + 1], cg);
            cb = fmaf(h0, Wrgb[(j + 0) * 3 + 2], cb);
            cr = fmaf(h1, Wrgb[(j + 1) * 3 + 0], cr);
            cg = fmaf(h1, Wrgb[(j + 1) * 3 + 1], cg);
            cb = fmaf(h1, Wrgb[(j + 1) * 3 + 2], cb);
            cr = fmaf(h2, Wrgb[(j + 2) * 3 + 0], cr);
            cg = fmaf(h2, Wrgb[(j + 2) * 3 + 1], cg);
            cb = fmaf(h2, Wrgb[(j + 2) * 3 + 2], cb);
            cr = fmaf(h3, Wrgb[(j + 3) * 3 + 0], cr);
            cg = fmaf(h3, Wrgb[(j + 3) * 3 + 1], cg);
            cb = fmaf(h3, Wrgb[(j + 3) * 3 + 2], cb);
        }
        const float tau = fmaxf(sigma, 0.0f) * step;
        alpha = 1.0f - __expf(-tau);
        r = 1.0f / (1.0f + __expf(-cr));
        g = 1.0f / (1.0f + __expf(-cg));
        b = 1.0f / (1.0f + __expf(-cb));
    }

    // ---- composite (per ray): warp-shuffle scan + 4-warp combine ----
    const float f = 1.0f - alpha + 1e-10f;
    float incl = f;
    #pragma unroll
    for (int off = 1; off < 32; off <<= 1) {
        const float v = __shfl_up_sync(0xffffffffu, incl, off);
        if (lane >= off) incl *= v;
    }
    const float wtot = __shfl_sync(0xffffffffu, incl, 31);
    if (lane == 0) sWprod[warp] = wtot;
    __syncthreads();

    float pre = 1.0f;
    #pragma unroll
    for (int i = 0; i < 4; i++) if (i < warpInRay) pre *= sWprod[rayLocal * 4 + i];

    float excl = __shfl_up_sync(0xffffffffu, incl, 1);
    if (lane == 0) excl = 1.0f;

    const float w = alpha * pre * excl;
    float wr = w * r, wg = w * g, wb = w * b;
    #pragma unroll
    for (int off = 16; off > 0; off >>= 1) {
        wr += __shfl_down_sync(0xffffffffu, wr, off);
        wg += __shfl_down_sync(0xffffffffu, wg, off);
        wb += __shfl_down_sync(0xffffffffu, wb, off);
    }
    if (lane == 0) { sSum[warp * 3 + 0] = wr; sSum[warp * 3 + 1] = wg; sSum[warp * 3 + 2] = wb; }
    __syncthreads();

    if (samp == 0) {
        const int base = rayLocal * 4;
        const float no_hit = sWprod[base] * sWprod[base + 1] * sWprod[base + 2] * sWprod[base + 3];
        float c0 = no_hit, c1 = no_hit, c2 = no_hit;
        #pragma unroll
        for (int i = 0; i < 4; i++) {
            c0 += sSum[(base + i) * 3 + 0];
            c1 += sSum[(base + i) * 3 + 1];
            c2 += sSum[(base + i) * 3 + 2];
        }
        out[ray * 3 + 0] = c0;
        out[ray * 3 + 1] = c1;
        out[ray * 3 + 2] = c2;
    }
}

extern "C" void kernel_launch(void* const* d_in, const int* in_sizes, int n_in,
                              void* d_out, int out_size)
{
    const float* rays_o  = (const float*)d_in[0];
    const float* rays_d  = (const float*)d_in[1];
    const float* nearv   = (const float*)d_in[2];
    const float* farv    = (const float*)d_in[3];
    const float* jitter  = (const float*)d_in[4];
    const float* density = (const float*)d_in[5];
    const float* W1      = (const float*)d_in[6];
    const float* b1      = (const float*)d_in[7];
    const float* W2      = (const float*)d_in[8];
    const float* b2      = (const float*)d_in[9];
    const float* Wsig    = (const float*)d_in[10];
    const float* bsig    = (const float*)d_in[11];
    const float* Wrgb    = (const float*)d_in[12];
    const float* brgb    = (const float*)d_in[13];

    const int n_rays = in_sizes[2];   // near has one entry per ray

    cudaFuncSetAttribute(render_kernel, cudaFuncAttributeMaxDynamicSharedMemorySize, SMEM_BYTES);

    pack_w2_kernel<<<(H * H + 127) / 128, 128>>>(W2);
    render_kernel<<<n_rays / RPB, NT, SMEM_BYTES>>>(rays_o, rays_d, nearv, farv, jitter, density,
                                                    W1, b1, b2, Wsig, bsig, Wrgb, brgb,
                                                    (float*)d_out);
}

// round 10
// speedup vs baseline: 1.1541x; 1.1541x over previous
#include <cuda_runtime.h>
#include <cuda_fp16.h>
#include <mma.h>

using namespace nvcuda;

#define S 128
#define H 64
#define LDH 72     // leading dim for half tiles (144 B = 9*16, LDSM conflict-free)
#define LDF 68     // leading dim for float h2 rows (272 B = 17*16, conflict-free float4)

// Dynamic shared memory layout (bytes):
//   [0, 36864)      aliased: { h1_hi half[128*LDH] @0 ; h1_lo half[128*LDH] @18432 }
//                   later:   h2 float[128*LDF] = 34816 B (fits)
//   [36864, 46080)  W2_hi half[64*LDH]  (copied pre-packed from global)
//   [46080, 55296)  W2_lo half[64*LDH]
//   [55296, 55312)  sWprod float[4]
//   [55312, 55360)  sSum  float[4][3]
#define SMEM_BYTES 55360

// Pre-split W2 (Markidis hi/lo fp16) in the FINAL padded smem layout,
// packed once per launch. __device__ globals are zero-initialized, so the
// LDH padding columns stay zero.
__device__ __align__(16) __half gW2hi[H * LDH];
__device__ __align__(16) __half gW2lo[H * LDH];

__global__ void pack_w2_kernel(const float* __restrict__ W2)
{
    const int i = blockIdx.x * blockDim.x + threadIdx.x;
    if (i < H * H) {
        const int k = i >> 6, j = i & 63;
        const float w = W2[i];
        const __half hi = __float2half_rn(w);
        gW2hi[k * LDH + j] = hi;
        gW2lo[k * LDH + j] = __float2half_rn(w - __half2float(hi));
    }
}

__global__ __launch_bounds__(128, 4)
void render_kernel(const float* __restrict__ rays_o,
                   const float* __restrict__ rays_d,
                   const float* __restrict__ nearv,
                   const float* __restrict__ farv,
                   const float* __restrict__ jitter,
                   const float* __restrict__ density,
                   const float* __restrict__ W1,
                   const float* __restrict__ b1,
                   const float* __restrict__ b2,
                   const float* __restrict__ Wsig,
                   const float* __restrict__ bsig,
                   const float* __restrict__ Wrgb,
                   const float* __restrict__ brgb,
                   float* __restrict__ out)
{
    extern __shared__ __align__(16) char smem[];
    __half* hH1hi = reinterpret_cast<__half*>(smem);
    __half* hH1lo = reinterpret_cast<__half*>(smem + 18432);
    float*  fH2   = reinterpret_cast<float*>(smem);            // aliases h1 pair
    __half* sW2hi = reinterpret_cast<__half*>(smem + 36864);
    __half* sW2lo = reinterpret_cast<__half*>(smem + 46080);
    float*  sWprod = reinterpret_cast<float*>(smem + 55296);   // [4]
    float*  sSum   = reinterpret_cast<float*>(smem + 55312);   // [4][3]

    const int t    = threadIdx.x;     // 0..127, sample index
    const int lane = t & 31;
    const int warp = t >> 5;          // 0..3
    const int ray  = blockIdx.x;

    // ---- per-sample ray setup + occupancy-grid mask ----
    const float ox = rays_o[ray * 3 + 0];
    const float oy = rays_o[ray * 3 + 1];
    const float oz = rays_o[ray * 3 + 2];
    const float dx = rays_d[ray * 3 + 0];
    const float dy = rays_d[ray * 3 + 1];
    const float dz = rays_d[ray * 3 + 2];
    const float nr = nearv[ray];
    const float fr = farv[ray];
    const float step = (fr - nr) * (1.0f / (float)S);
    const float z = nr + (float)t * step;

    const float p0x = ox + z * dx;
    const float p0y = oy + z * dy;
    const float p0z = oz + z * dz;
    const float ux = (p0x - (-1.25f)) / 2.5f;
    const float uy = (p0y - (-1.55f)) / 2.5f;
    const float uz = (p0z - (-1.25f)) / 2.5f;
    const int ix = (int)floorf(ux * 64.0f);
    const int iy = (int)floorf(uy * 64.0f);
    const int iz = (int)floorf(uz * 64.0f);
    const bool inb = (ix >= 0) & (ix < 64) & (iy >= 0) & (iy < 64) & (iz >= 0) & (iz < 64);
    const int cx = min(max(ix, 0), 63);
    const int cy = min(max(iy, 0), 63);
    const int cz = min(max(iz, 0), 63);
    const bool occ = density[(cx * 64 + cy) * 64 + cz] > 0.5f;
    const bool mask = occ && inb;

    // Whole-ray empty? -> exact white (1 - 0 + 1e-10 rounds to 1.0f).
    const int any_active = __syncthreads_or(mask ? 1 : 0);
    if (!any_active) {
        if (t == 0) {
            out[ray * 3 + 0] = 1.0f;
            out[ray * 3 + 1] = 1.0f;
            out[ray * 3 + 2] = 1.0f;
        }
        return;
    }

    // ---- copy pre-packed W2 hi/lo into shared (pure int4 memcpy) ----
    {
        const int4* src_hi = reinterpret_cast<const int4*>(gW2hi);
        const int4* src_lo = reinterpret_cast<const int4*>(gW2lo);
        int4* dst_hi = reinterpret_cast<int4*>(sW2hi);
        int4* dst_lo = reinterpret_cast<int4*>(sW2lo);
        #pragma unroll
        for (int i = t; i < (H * LDH) / 8; i += 128) {   // 576 int4 each
            dst_hi[i] = src_hi[i];
            dst_lo[i] = src_lo[i];
        }
    }

    // Warp-level skip: all-culled warps never have their MLP rows read.
    const unsigned wball = __ballot_sync(0xffffffffu, mask);
    const bool warp_active = (wball != 0u);

    const float zv = mask ? z : 0.0f;
    const float zj = zv + jitter[ray * S + t] * step;
    const float px = ox + zj * dx;
    const float py = oy + zj * dy;
    const float pz = oz + zj * dz;

    // ---- layer 1 (scalar fp32, K=3): vectorized 128-bit h1 stores ----
    if (warp_active) {
        uint4* hrowHi = reinterpret_cast<uint4*>(hH1hi + t * LDH);
        uint4* hrowLo = reinterpret_cast<uint4*>(hH1lo + t * LDH);
        #pragma unroll
        for (int j8 = 0; j8 < H; j8 += 8) {
            uint4 vhi, vlo;
            __half2* phi = reinterpret_cast<__half2*>(&vhi);
            __half2* plo = reinterpret_cast<__half2*>(&vlo);
            #pragma unroll
            for (int u = 0; u < 4; u++) {
                const int j = j8 + u * 2;
                float v0 = b1[j];
                v0 = fmaf(px, W1[j], v0);
                v0 = fmaf(py, W1[H + j], v0);
                v0 = fmaf(pz, W1[2 * H + j], v0);
                v0 = fmaxf(v0, 0.0f);
                float v1 = b1[j + 1];
                v1 = fmaf(px, W1[j + 1], v1);
                v1 = fmaf(py, W1[H + j + 1], v1);
                v1 = fmaf(pz, W1[2 * H + j + 1], v1);
                v1 = fmaxf(v1, 0.0f);
                const __half h0 = __float2half_rn(v0);
                const __half h1 = __float2half_rn(v1);
                const __half l0 = __float2half_rn(v0 - __half2float(h0));
                const __half l1 = __float2half_rn(v1 - __half2float(h1));
                phi[u] = __halves2half2(h0, h1);
                plo[u] = __halves2half2(l0, l1);
            }
            hrowHi[j8 >> 3] = vhi;
            hrowLo[j8 >> 3] = vlo;
        }
    }
    __syncthreads();   // h1 rows + W2 smem copy visible to all warps

    // ---- layer 2: h2 = h_hi*w_hi + h_hi*w_lo + h_lo*w_hi (fp32 accum) ----
    wmma::fragment<wmma::accumulator, 16, 16, 16, float> c[2][4];
    if (warp_active) {
        #pragma unroll
        for (int mt = 0; mt < 2; mt++)
            #pragma unroll
            for (int nt = 0; nt < 4; nt++)
                wmma::fill_fragment(c[mt][nt], 0.0f);

        #pragma unroll
        for (int k = 0; k < 4; k++) {
            wmma::fragment<wmma::matrix_a, 16, 16, 16, __half, wmma::row_major> aHi0, aHi1, aLo0, aLo1;
            wmma::load_matrix_sync(aHi0, hH1hi + (warp * 32) * LDH + k * 16, LDH);
            wmma::load_matrix_sync(aHi1, hH1hi + (warp * 32 + 16) * LDH + k * 16, LDH);
            wmma::load_matrix_sync(aLo0, hH1lo + (warp * 32) * LDH + k * 16, LDH);
            wmma::load_matrix_sync(aLo1, hH1lo + (warp * 32 + 16) * LDH + k * 16, LDH);
            #pragma unroll
            for (int nt = 0; nt < 4; nt++) {
                wmma::fragment<wmma::matrix_b, 16, 16, 16, __half, wmma::row_major> bHi, bLo;
                wmma::load_matrix_sync(bHi, sW2hi + (k * 16) * LDH + nt * 16, LDH);
                wmma::load_matrix_sync(bLo, sW2lo + (k * 16) * LDH + nt * 16, LDH);
                wmma::mma_sync(c[0][nt], aHi0, bHi, c[0][nt]);
                wmma::mma_sync(c[1][nt], aHi1, bHi, c[1][nt]);
                wmma::mma_sync(c[0][nt], aHi0, bLo, c[0][nt]);
                wmma::mma_sync(c[1][nt], aHi1, bLo, c[1][nt]);
                wmma::mma_sync(c[0][nt], aLo0, bHi, c[0][nt]);
                wmma::mma_sync(c[1][nt], aLo1, bHi, c[1][nt]);
            }
        }
    }

    // fH2 aliases the h1 buffers: all MMA reads must finish before stores.
    __syncthreads();
    if (warp_active) {
        #pragma unroll
        for (int mt = 0; mt < 2; mt++)
            #pragma unroll
            for (int nt = 0; nt < 4; nt++)
                wmma::store_matrix_sync(fH2 + (warp * 32 + mt * 16) * LDF + nt * 16,
                                        c[mt][nt], LDF, wmma::mem_row_major);
    }
    __syncthreads();

    // ---- heads (scalar fp32), only for active samples; weights via uniform LDG ----
    float alpha = 0.0f, r = 0.0f, g = 0.0f, b = 0.0f;
    if (mask) {
        float sigma = bsig[0];
        float cr = brgb[0], cg = brgb[1], cb = brgb[2];
        const float4* hrow = reinterpret_cast<const float4*>(fH2 + t * LDF);
        #pragma unroll
        for (int jq = 0; jq < 16; jq++) {
            const float4 hv = hrow[jq];
            const int j = jq * 4;
            const float h0 = fmaxf(hv.x + b2[j + 0], 0.0f);
            const float h1 = fmaxf(hv.y + b2[j + 1], 0.0f);
            const float h2 = fmaxf(hv.z + b2[j + 2], 0.0f);
            const float h3 = fmaxf(hv.w + b2[j + 3], 0.0f);
            sigma = fmaf(h0, Wsig[j + 0], sigma);
            sigma = fmaf(h1, Wsig[j + 1], sigma);
            sigma = fmaf(h2, Wsig[j + 2], sigma);
            sigma = fmaf(h3, Wsig[j + 3], sigma);
            cr = fmaf(h0, Wrgb[(j + 0) * 3 + 0], cr);
            cg = fmaf(h0, Wrgb[(j + 0) * 3 + 1], cg);
            cb = fmaf(h0, Wrgb[(j + 0) * 3 + 2], cb);
            cr = fmaf(h1, Wrgb[(j + 1) * 3 + 0], cr);
            cg = fmaf(h1, Wrgb[(j + 1) * 3 + 1], cg);
            cb = fmaf(h1, Wrgb[(j + 1) * 3 + 2], cb);
            cr = fmaf(h2, Wrgb[(j + 2) * 3 + 0], cr);
            cg = fmaf(h2, Wrgb[(j + 2) * 3 + 1], cg);
            cb = fmaf(h2, Wrgb[(j + 2) * 3 + 2], cb);
            cr = fmaf(h3, Wrgb[(j + 3) * 3 + 0], cr);
            cg = fmaf(h3, Wrgb[(j + 3) * 3 + 1], cg);
            cb = fmaf(h3, Wrgb[(j + 3) * 3 + 2], cb);
        }
        const float tau = fmaxf(sigma, 0.0f) * step;
        alpha = 1.0f - __expf(-tau);
        r = 1.0f / (1.0f + __expf(-cr));
        g = 1.0f / (1.0f + __expf(-cg));
        b = 1.0f / (1.0f + __expf(-cb));
    }

    // ---- composite: warp-shuffle scan + cross-warp combine ----
    const float f = 1.0f - alpha + 1e-10f;
    float incl = f;
    #pragma unroll
    for (int off = 1; off < 32; off <<= 1) {
        const float v = __shfl_up_sync(0xffffffffu, incl, off);
        if (lane >= off) incl *= v;
    }
    const float wtot = __shfl_sync(0xffffffffu, incl, 31);
    if (lane == 0) sWprod[warp] = wtot;
    __syncthreads();

    float pre = 1.0f;
    #pragma unroll
    for (int i = 0; i < 4; i++) if (i < warp) pre *= sWprod[i];

    float excl = __shfl_up_sync(0xffffffffu, incl, 1);
    if (lane == 0) excl = 1.0f;

    const float w = alpha * pre * excl;
    float wr = w * r, wg = w * g, wb = w * b;
    #pragma unroll
    for (int off = 16; off > 0; off >>= 1) {
        wr += __shfl_down_sync(0xffffffffu, wr, off);
        wg += __shfl_down_sync(0xffffffffu, wg, off);
        wb += __shfl_down_sync(0xffffffffu, wb, off);
    }
    if (lane == 0) { sSum[warp * 3 + 0] = wr; sSum[warp * 3 + 1] = wg; sSum[warp * 3 + 2] = wb; }
    __syncthreads();

    if (t == 0) {
        const float no_hit = sWprod[0] * sWprod[1] * sWprod[2] * sWprod[3];
        float c0 = no_hit, c1 = no_hit, c2 = no_hit;
        #pragma unroll
        for (int i = 0; i < 4; i++) {
            c0 += sSum[i * 3 + 0];
            c1 += sSum[i * 3 + 1];
            c2 += sSum[i * 3 + 2];
        }
        out[ray * 3 + 0] = c0;
        out[ray * 3 + 1] = c1;
        out[ray * 3 + 2] = c2;
    }
}

extern "C" void kernel_launch(void* const* d_in, const int* in_sizes, int n_in,
                              void* d_out, int out_size)
{
    const float* rays_o  = (const float*)d_in[0];
    const float* rays_d  = (const float*)d_in[1];
    const float* nearv   = (const float*)d_in[2];
    const float* farv    = (const float*)d_in[3];
    const float* jitter  = (const float*)d_in[4];
    const float* density = (const float*)d_in[5];
    const float* W1      = (const float*)d_in[6];
    const float* b1      = (const float*)d_in[7];
    const float* W2      = (const float*)d_in[8];
    const float* b2      = (const float*)d_in[9];
    const float* Wsig    = (const float*)d_in[10];
    const float* bsig    = (const float*)d_in[11];
    const float* Wrgb    = (const float*)d_in[12];
    const float* brgb    = (const float*)d_in[13];

    const int n_rays = in_sizes[2];   // near has one entry per ray

    cudaFuncSetAttribute(render_kernel, cudaFuncAttributeMaxDynamicSharedMemorySize, SMEM_BYTES);

    pack_w2_kernel<<<(H * H + 127) / 128, 128>>>(W2);
    render_kernel<<<n_rays, 128, SMEM_BYTES>>>(rays_o, rays_d, nearv, farv, jitter, density,
                                               W1, b1, b2, Wsig, bsig, Wrgb, brgb,
                                               (float*)d_out);
}

// round 11
// speedup vs baseline: 1.3515x; 1.1710x over previous
#include <cuda_runtime.h>
#include <cuda_fp16.h>
#include <cstring>

#define S 128
#define H 64
#define LDH 72     // leading dim (halves) for h1 tiles; 144 B = 9*16B granules -> ldmatrix conflict-free

// Dynamic shared memory layout (bytes):
//   [0, 18432)      h1_hi half[128*LDH]  (cols 64..71 of rows 0..63 hold B'hi = [Wsig|Wrgb|0] hi)
//                   after MMA phase: first 2048 B alias sHead float[128][4]
//   [18432, 36864)  h1_lo half[128*LDH]  (cols 64..71 of rows 0..63 hold B'lo)
//   [36864, 46080)  W2_hi half[64*LDH]
//   [46080, 55296)  W2_lo half[64*LDH]
//   [55296, 55312)  sWprod float[4]
//   [55312, 55360)  sSum  float[4][3]
#define SMEM_BYTES 55360

// Pre-split weights (Markidis hi/lo fp16), packed once per launch.
__device__ __align__(16) __half gW2hi[H * LDH];
__device__ __align__(16) __half gW2lo[H * LDH];
__device__ __align__(16) __half gBphi[H * 8];   // [k][n]: n0=Wsig, n1..3=Wrgb, n4..7=0
__device__ __align__(16) __half gBplo[H * 8];

__global__ void pack_kernel(const float* __restrict__ W2,
                            const float* __restrict__ Wsig,
                            const float* __restrict__ Wrgb)
{
    const int i = blockIdx.x * blockDim.x + threadIdx.x;
    if (i < H * H) {
        const int k = i >> 6, j = i & 63;
        const float w = W2[i];
        const __half hi = __float2half_rn(w);
        gW2hi[k * LDH + j] = hi;
        gW2lo[k * LDH + j] = __float2half_rn(w - __half2float(hi));
    }
    if (i < H) {
        float w[8];
        w[0] = Wsig[i];
        w[1] = Wrgb[i * 3 + 0];
        w[2] = Wrgb[i * 3 + 1];
        w[3] = Wrgb[i * 3 + 2];
        w[4] = 0.0f; w[5] = 0.0f; w[6] = 0.0f; w[7] = 0.0f;
        #pragma unroll
        for (int n = 0; n < 8; n++) {
            const __half hi = __float2half_rn(w[n]);
            gBphi[i * 8 + n] = hi;
            gBplo[i * 8 + n] = __float2half_rn(w[n] - __half2float(hi));
        }
    }
}

__device__ __forceinline__ void ldsm_x4(unsigned& r0, unsigned& r1, unsigned& r2, unsigned& r3, unsigned a) {
    asm volatile("ldmatrix.sync.aligned.m8n8.x4.shared.b16 {%0,%1,%2,%3}, [%4];"
                 : "=r"(r0), "=r"(r1), "=r"(r2), "=r"(r3) : "r"(a));
}
__device__ __forceinline__ void ldsm_x2t(unsigned& r0, unsigned& r1, unsigned a) {
    asm volatile("ldmatrix.sync.aligned.m8n8.x2.trans.shared.b16 {%0,%1}, [%2];"
                 : "=r"(r0), "=r"(r1) : "r"(a));
}
__device__ __forceinline__ void mma16816(float* d, unsigned a0, unsigned a1, unsigned a2, unsigned a3,
                                         unsigned b0, unsigned b1) {
    asm volatile("mma.sync.aligned.m16n8k16.row.col.f32.f16.f16.f32 "
                 "{%0,%1,%2,%3},{%4,%5,%6,%7},{%8,%9},{%0,%1,%2,%3};"
                 : "+f"(d[0]), "+f"(d[1]), "+f"(d[2]), "+f"(d[3])
                 : "r"(a0), "r"(a1), "r"(a2), "r"(a3), "r"(b0), "r"(b1));
}
__device__ __forceinline__ unsigned h2u(__half2 h) { unsigned u; memcpy(&u, &h, 4); return u; }

__global__ __launch_bounds__(128, 4)
void render_kernel(const float* __restrict__ rays_o,
                   const float* __restrict__ rays_d,
                   const float* __restrict__ nearv,
                   const float* __restrict__ farv,
                   const float* __restrict__ jitter,
                   const float* __restrict__ density,
                   const float* __restrict__ W1,
                   const float* __restrict__ b1,
                   const float* __restrict__ b2,
                   const float* __restrict__ bsig,
                   const float* __restrict__ brgb,
                   float* __restrict__ out)
{
    extern __shared__ __align__(16) char smem[];
    __half* hH1hi = reinterpret_cast<__half*>(smem);
    __half* hH1lo = reinterpret_cast<__half*>(smem + 18432);
    float*  sHead = reinterpret_cast<float*>(smem);            // aliases h1hi after MMA phase
    __half* sW2hi = reinterpret_cast<__half*>(smem + 36864);
    __half* sW2lo = reinterpret_cast<__half*>(smem + 46080);
    float*  sWprod = reinterpret_cast<float*>(smem + 55296);   // [4]
    float*  sSum   = reinterpret_cast<float*>(smem + 55312);   // [4][3]

    const int t    = threadIdx.x;     // 0..127, sample index
    const int lane = t & 31;
    const int warp = t >> 5;          // 0..3
    const int g    = lane >> 2;       // fragment row group
    const int q    = lane & 3;        // fragment col group
    const int ray  = blockIdx.x;

    // ---- per-sample ray setup + occupancy-grid mask ----
    const float ox = rays_o[ray * 3 + 0];
    const float oy = rays_o[ray * 3 + 1];
    const float oz = rays_o[ray * 3 + 2];
    const float dx = rays_d[ray * 3 + 0];
    const float dy = rays_d[ray * 3 + 1];
    const float dz = rays_d[ray * 3 + 2];
    const float nr = nearv[ray];
    const float fr = farv[ray];
    const float step = (fr - nr) * (1.0f / (float)S);
    const float z = nr + (float)t * step;

    const float p0x = ox + z * dx;
    const float p0y = oy + z * dy;
    const float p0z = oz + z * dz;
    const float ux = (p0x - (-1.25f)) / 2.5f;
    const float uy = (p0y - (-1.55f)) / 2.5f;
    const float uz = (p0z - (-1.25f)) / 2.5f;
    const int ix = (int)floorf(ux * 64.0f);
    const int iy = (int)floorf(uy * 64.0f);
    const int iz = (int)floorf(uz * 64.0f);
    const bool inb = (ix >= 0) & (ix < 64) & (iy >= 0) & (iy < 64) & (iz >= 0) & (iz < 64);
    const int cx = min(max(ix, 0), 63);
    const int cy = min(max(iy, 0), 63);
    const int cz = min(max(iz, 0), 63);
    const bool occ = density[(cx * 64 + cy) * 64 + cz] > 0.5f;
    const bool mask = occ && inb;

    const int any_active = __syncthreads_or(mask ? 1 : 0);
    if (!any_active) {
        if (t == 0) {
            out[ray * 3 + 0] = 1.0f;
            out[ray * 3 + 1] = 1.0f;
            out[ray * 3 + 2] = 1.0f;
        }
        return;
    }

    // ---- stage W2 hi/lo (int4 memcpy) + B' into h1 padding columns ----
    {
        const int4* src_hi = reinterpret_cast<const int4*>(gW2hi);
        const int4* src_lo = reinterpret_cast<const int4*>(gW2lo);
        int4* dst_hi = reinterpret_cast<int4*>(sW2hi);
        int4* dst_lo = reinterpret_cast<int4*>(sW2lo);
        #pragma unroll
        for (int i = t; i < (H * LDH) / 8; i += 128) {
            dst_hi[i] = src_hi[i];
            dst_lo[i] = src_lo[i];
        }
        // B' rows: one uint4 (8 halves) per row; threads 0-63 hi, 64-127 lo
        const int r = t & 63;
        const int4 v = (t < 64) ? reinterpret_cast<const int4*>(gBphi)[r]
                                : reinterpret_cast<const int4*>(gBplo)[r];
        __half* base = (t < 64) ? hH1hi : hH1lo;
        *reinterpret_cast<int4*>(base + r * LDH + 64) = v;
    }

    const unsigned wball = __ballot_sync(0xffffffffu, mask);
    const bool warp_active = (wball != 0u);

    const float zv = mask ? z : 0.0f;
    const float zj = zv + jitter[ray * S + t] * step;
    const float px = ox + zj * dx;
    const float py = oy + zj * dy;
    const float pz = oz + zj * dz;

    // ---- layer 1 (scalar fp32, K=3): vectorized 128-bit h1 stores ----
    if (warp_active) {
        uint4* hrowHi = reinterpret_cast<uint4*>(hH1hi + t * LDH);
        uint4* hrowLo = reinterpret_cast<uint4*>(hH1lo + t * LDH);
        #pragma unroll
        for (int j8 = 0; j8 < H; j8 += 8) {
            uint4 vhi, vlo;
            __half2* phi = reinterpret_cast<__half2*>(&vhi);
            __half2* plo = reinterpret_cast<__half2*>(&vlo);
            #pragma unroll
            for (int u = 0; u < 4; u++) {
                const int j = j8 + u * 2;
                float v0 = b1[j];
                v0 = fmaf(px, W1[j], v0);
                v0 = fmaf(py, W1[H + j], v0);
                v0 = fmaf(pz, W1[2 * H + j], v0);
                v0 = fmaxf(v0, 0.0f);
                float v1 = b1[j + 1];
                v1 = fmaf(px, W1[j + 1], v1);
                v1 = fmaf(py, W1[H + j + 1], v1);
                v1 = fmaf(pz, W1[2 * H + j + 1], v1);
                v1 = fmaxf(v1, 0.0f);
                const __half h0 = __float2half_rn(v0);
                const __half h1 = __float2half_rn(v1);
                phi[u] = __halves2half2(h0, h1);
                plo[u] = __halves2half2(__float2half_rn(v0 - __half2float(h0)),
                                        __float2half_rn(v1 - __half2float(h1)));
            }
            hrowHi[j8 >> 3] = vhi;
            hrowLo[j8 >> 3] = vlo;
        }
    }
    __syncthreads();   // h1 + W2 + B' staged

    const unsigned h1hiU = (unsigned)__cvta_generic_to_shared(hH1hi);
    const unsigned h1loU = (unsigned)__cvta_generic_to_shared(hH1lo);
    const unsigned w2hiU = (unsigned)__cvta_generic_to_shared(sW2hi);
    const unsigned w2loU = (unsigned)__cvta_generic_to_shared(sW2lo);

    float hc[2][4];                       // heads C' (sigma,r | g,b logits)
    #pragma unroll
    for (int mt = 0; mt < 2; mt++)
        #pragma unroll
        for (int u = 0; u < 4; u++) hc[mt][u] = 0.0f;

    if (warp_active) {
        float C[2][8][4];                 // h2 accumulators, fully register-resident
        #pragma unroll
        for (int mt = 0; mt < 2; mt++)
            #pragma unroll
            for (int nt = 0; nt < 8; nt++)
                #pragma unroll
                for (int u = 0; u < 4; u++) C[mt][nt][u] = 0.0f;

        // A/B address lane patterns
        const int arow = lane & 15;               // rows within tile
        const int acol = (lane >> 4) * 8;         // k-half select
        const int brow = lane & 15;               // k rows for trans B

        // ---- main GEMM: k-outer, A frags resident per k ----
        #pragma unroll
        for (int k = 0; k < 4; k++) {
            unsigned aHi[2][4], aLo[2][4];
            #pragma unroll
            for (int mt = 0; mt < 2; mt++) {
                const unsigned off = (unsigned)(((warp * 32 + mt * 16 + arow) * LDH + k * 16 + acol) * 2);
                ldsm_x4(aHi[mt][0], aHi[mt][1], aHi[mt][2], aHi[mt][3], h1hiU + off);
                ldsm_x4(aLo[mt][0], aLo[mt][1], aLo[mt][2], aLo[mt][3], h1loU + off);
            }
            #pragma unroll
            for (int nt = 0; nt < 8; nt++) {
                const unsigned boff = (unsigned)(((k * 16 + brow) * LDH + nt * 8) * 2);
                unsigned bh0, bh1, bl0, bl1;
                ldsm_x2t(bh0, bh1, w2hiU + boff);
                ldsm_x2t(bl0, bl1, w2loU + boff);
                #pragma unroll
                for (int mt = 0; mt < 2; mt++) {
                    mma16816(C[mt][nt], aHi[mt][0], aHi[mt][1], aHi[mt][2], aHi[mt][3], bh0, bh1);
                    mma16816(C[mt][nt], aHi[mt][0], aHi[mt][1], aHi[mt][2], aHi[mt][3], bl0, bl1);
                    mma16816(C[mt][nt], aLo[mt][0], aLo[mt][1], aLo[mt][2], aLo[mt][3], bh0, bh1);
                }
            }
        }

        // ---- heads: relu(h2 + b2) @ [Wsig|Wrgb], A' packed from C in registers ----
        #pragma unroll
        for (int ntp = 0; ntp < 4; ntp++) {
            const unsigned bpoff = (unsigned)(((ntp * 16 + brow) * LDH + 64) * 2);
            unsigned bph0, bph1, bpl0, bpl1;
            ldsm_x2t(bph0, bph1, h1hiU + bpoff);
            ldsm_x2t(bpl0, bpl1, h1loU + bpoff);
            const float2 bb0 = *reinterpret_cast<const float2*>(b2 + (2 * ntp) * 8 + 2 * q);
            const float2 bb1 = *reinterpret_cast<const float2*>(b2 + (2 * ntp + 1) * 8 + 2 * q);
            #pragma unroll
            for (int mt = 0; mt < 2; mt++) {
                unsigned aH[4], aL[4];
                #pragma unroll
                for (int sub = 0; sub < 2; sub++) {
                    const float* c = C[mt][2 * ntp + sub];
                    const float2 bb = sub ? bb1 : bb0;
                    const float v0 = fmaxf(c[0] + bb.x, 0.0f);
                    const float v1 = fmaxf(c[1] + bb.y, 0.0f);
                    const float v2 = fmaxf(c[2] + bb.x, 0.0f);
                    const float v3 = fmaxf(c[3] + bb.y, 0.0f);
                    const __half2 h01 = __floats2half2_rn(v0, v1);
                    const __half2 h23 = __floats2half2_rn(v2, v3);
                    aH[2 * sub + 0] = h2u(h01);
                    aH[2 * sub + 1] = h2u(h23);
                    aL[2 * sub + 0] = h2u(__floats2half2_rn(v0 - __low2float(h01), v1 - __high2float(h01)));
                    aL[2 * sub + 1] = h2u(__floats2half2_rn(v2 - __low2float(h23), v3 - __high2float(h23)));
                }
                mma16816(hc[mt], aH[0], aH[1], aH[2], aH[3], bph0, bph1);
                mma16816(hc[mt], aH[0], aH[1], aH[2], aH[3], bpl0, bpl1);
                mma16816(hc[mt], aL[0], aL[1], aL[2], aL[3], bph0, bph1);
            }
        }
    }

    __syncthreads();   // all h1/W2/B' smem reads done; safe to overwrite with sHead

    // ---- scatter head logits to per-sample slots (q=0: sigma,r ; q=1: g,b) ----
    if (warp_active && q < 2) {
        #pragma unroll
        for (int mt = 0; mt < 2; mt++) {
            const int s0 = warp * 32 + mt * 16 + g;
            float2 v01 = make_float2(hc[mt][0], hc[mt][1]);
            float2 v23 = make_float2(hc[mt][2], hc[mt][3]);
            *reinterpret_cast<float2*>(sHead + s0 * 4 + q * 2) = v01;
            *reinterpret_cast<float2*>(sHead + (s0 + 8) * 4 + q * 2) = v23;
        }
    }
    __syncthreads();

    // ---- per-sample nonlinearities + composite ----
    float alpha = 0.0f, r = 0.0f, gg = 0.0f, b = 0.0f;
    if (mask) {
        const float4 hv = *reinterpret_cast<const float4*>(sHead + t * 4);
        const float sigma = hv.x + bsig[0];
        const float cr = hv.y + brgb[0];
        const float cg = hv.z + brgb[1];
        const float cb = hv.w + brgb[2];
        const float tau = fmaxf(sigma, 0.0f) * step;
        alpha = 1.0f - __expf(-tau);
        r  = 1.0f / (1.0f + __expf(-cr));
        gg = 1.0f / (1.0f + __expf(-cg));
        b  = 1.0f / (1.0f + __expf(-cb));
    }

    const float f = 1.0f - alpha + 1e-10f;
    float incl = f;
    #pragma unroll
    for (int off = 1; off < 32; off <<= 1) {
        const float v = __shfl_up_sync(0xffffffffu, incl, off);
        if (lane >= off) incl *= v;
    }
    const float wtot = __shfl_sync(0xffffffffu, incl, 31);
    if (lane == 0) sWprod[warp] = wtot;
    __syncthreads();

    float pre = 1.0f;
    #pragma unroll
    for (int i = 0; i < 4; i++) if (i < warp) pre *= sWprod[i];

    float excl = __shfl_up_sync(0xffffffffu, incl, 1);
    if (lane == 0) excl = 1.0f;

    const float w = alpha * pre * excl;
    float wr = w * r, wg = w * gg, wb = w * b;
    #pragma unroll
    for (int off = 16; off > 0; off >>= 1) {
        wr += __shfl_down_sync(0xffffffffu, wr, off);
        wg += __shfl_down_sync(0xffffffffu, wg, off);
        wb += __shfl_down_sync(0xffffffffu, wb, off);
    }
    if (lane == 0) { sSum[warp * 3 + 0] = wr; sSum[warp * 3 + 1] = wg; sSum[warp * 3 + 2] = wb; }
    __syncthreads();

    if (t == 0) {
        const float no_hit = sWprod[0] * sWprod[1] * sWprod[2] * sWprod[3];
        float c0 = no_hit, c1 = no_hit, c2 = no_hit;
        #pragma unroll
        for (int i = 0; i < 4; i++) {
            c0 += sSum[i * 3 + 0];
            c1 += sSum[i * 3 + 1];
            c2 += sSum[i * 3 + 2];
        }
        out[ray * 3 + 0] = c0;
        out[ray * 3 + 1] = c1;
        out[ray * 3 + 2] = c2;
    }
}

extern "C" void kernel_launch(void* const* d_in, const int* in_sizes, int n_in,
                              void* d_out, int out_size)
{
    const float* rays_o  = (const float*)d_in[0];
    const float* rays_d  = (const float*)d_in[1];
    const float* nearv   = (const float*)d_in[2];
    const float* farv    = (const float*)d_in[3];
    const float* jitter  = (const float*)d_in[4];
    const float* density = (const float*)d_in[5];
    const float* W1      = (const float*)d_in[6];
    const float* b1      = (const float*)d_in[7];
    const float* W2      = (const float*)d_in[8];
    const float* b2      = (const float*)d_in[9];
    const float* Wsig    = (const float*)d_in[10];
    const float* bsig    = (const float*)d_in[11];
    const float* Wrgb    = (const float*)d_in[12];
    const float* brgb    = (const float*)d_in[13];

    const int n_rays = in_sizes[2];   // near has one entry per ray

    cudaFuncSetAttribute(render_kernel, cudaFuncAttributeMaxDynamicSharedMemorySize, SMEM_BYTES);

    pack_kernel<<<(H * H + 127) / 128, 128>>>(W2, Wsig, Wrgb);
    render_kernel<<<n_rays, 128, SMEM_BYTES>>>(rays_o, rays_d, nearv, farv, jitter, density,
                                               W1, b1, b2, bsig, brgb,
                                               (float*)d_out);
}

// round 12
// speedup vs baseline: 1.4028x; 1.0380x over previous
#include <cuda_runtime.h>
#include <cuda_fp16.h>
#include <cstring>

#define S 128
#define H 64
#define LDH 72     // leading dim (halves) for h1 tiles; 144 B = 9*16B granules -> ldmatrix conflict-free

// Dynamic shared memory layout (bytes):
//   [0, 18432)      h1_hi half[128*LDH]  (cols 64..71 of rows 0..63 hold B'hi = [Wsig|Wrgb|0] hi)
//   [18432, 36864)  h1_lo half[128*LDH]  (cols 64..71 of rows 0..63 hold B'lo)
//   [36864, 46080)  W2_hi half[64*LDH]
//   [46080, 55296)  W2_lo half[64*LDH]
//   [55296, 55312)  sWprod float[4]
//   [55312, 55360)  sSum  float[4][3]
#define SMEM_BYTES 55360

// Pre-split weights (Markidis hi/lo fp16), packed once per launch.
__device__ __align__(16) __half gW2hi[H * LDH];
__device__ __align__(16) __half gW2lo[H * LDH];
__device__ __align__(16) __half gBphi[H * 8];   // [k][n]: n0=Wsig, n1..3=Wrgb, n4..7=0
__device__ __align__(16) __half gBplo[H * 8];

__global__ void pack_kernel(const float* __restrict__ W2,
                            const float* __restrict__ Wsig,
                            const float* __restrict__ Wrgb)
{
    const int i = blockIdx.x * blockDim.x + threadIdx.x;
    if (i < H * H) {
        const int k = i >> 6, j = i & 63;
        const float w = W2[i];
        const __half hi = __float2half_rn(w);
        gW2hi[k * LDH + j] = hi;
        gW2lo[k * LDH + j] = __float2half_rn(w - __half2float(hi));
    }
    if (i < H) {
        float w[8];
        w[0] = Wsig[i];
        w[1] = Wrgb[i * 3 + 0];
        w[2] = Wrgb[i * 3 + 1];
        w[3] = Wrgb[i * 3 + 2];
        w[4] = 0.0f; w[5] = 0.0f; w[6] = 0.0f; w[7] = 0.0f;
        #pragma unroll
        for (int n = 0; n < 8; n++) {
            const __half hi = __float2half_rn(w[n]);
            gBphi[i * 8 + n] = hi;
            gBplo[i * 8 + n] = __float2half_rn(w[n] - __half2float(hi));
        }
    }
}

__device__ __forceinline__ void ldsm_x4(unsigned& r0, unsigned& r1, unsigned& r2, unsigned& r3, unsigned a) {
    asm volatile("ldmatrix.sync.aligned.m8n8.x4.shared.b16 {%0,%1,%2,%3}, [%4];"
                 : "=r"(r0), "=r"(r1), "=r"(r2), "=r"(r3) : "r"(a));
}
__device__ __forceinline__ void ldsm_x2t(unsigned& r0, unsigned& r1, unsigned a) {
    asm volatile("ldmatrix.sync.aligned.m8n8.x2.trans.shared.b16 {%0,%1}, [%2];"
                 : "=r"(r0), "=r"(r1) : "r"(a));
}
__device__ __forceinline__ void mma16816(float* d, unsigned a0, unsigned a1, unsigned a2, unsigned a3,
                                         unsigned b0, unsigned b1) {
    asm volatile("mma.sync.aligned.m16n8k16.row.col.f32.f16.f16.f32 "
                 "{%0,%1,%2,%3},{%4,%5,%6,%7},{%8,%9},{%0,%1,%2,%3};"
                 : "+f"(d[0]), "+f"(d[1]), "+f"(d[2]), "+f"(d[3])
                 : "r"(a0), "r"(a1), "r"(a2), "r"(a3), "r"(b0), "r"(b1));
}
__device__ __forceinline__ unsigned h2u(__half2 h) { unsigned u; memcpy(&u, &h, 4); return u; }

__global__ __launch_bounds__(128, 4)
void render_kernel(const float* __restrict__ rays_o,
                   const float* __restrict__ rays_d,
                   const float* __restrict__ nearv,
                   const float* __restrict__ farv,
                   const float* __restrict__ jitter,
                   const float* __restrict__ density,
                   const float* __restrict__ W1,
                   const float* __restrict__ b1,
                   const float* __restrict__ b2,
                   const float* __restrict__ bsig,
                   const float* __restrict__ brgb,
                   float* __restrict__ out)
{
    extern __shared__ __align__(16) char smem[];
    __half* hH1hi = reinterpret_cast<__half*>(smem);
    __half* hH1lo = reinterpret_cast<__half*>(smem + 18432);
    __half* sW2hi = reinterpret_cast<__half*>(smem + 36864);
    __half* sW2lo = reinterpret_cast<__half*>(smem + 46080);
    float*  sWprod = reinterpret_cast<float*>(smem + 55296);   // [4]
    float*  sSum   = reinterpret_cast<float*>(smem + 55312);   // [4][3]

    const int t    = threadIdx.x;     // 0..127, sample index
    const int lane = t & 31;
    const int warp = t >> 5;          // 0..3
    const int ray  = blockIdx.x;

    // ---- per-sample ray setup + occupancy-grid mask ----
    const float ox = rays_o[ray * 3 + 0];
    const float oy = rays_o[ray * 3 + 1];
    const float oz = rays_o[ray * 3 + 2];
    const float dx = rays_d[ray * 3 + 0];
    const float dy = rays_d[ray * 3 + 1];
    const float dz = rays_d[ray * 3 + 2];
    const float nr = nearv[ray];
    const float fr = farv[ray];
    const float step = (fr - nr) * (1.0f / (float)S);
    const float z = nr + (float)t * step;

    const float p0x = ox + z * dx;
    const float p0y = oy + z * dy;
    const float p0z = oz + z * dz;
    const float ux = (p0x - (-1.25f)) / 2.5f;
    const float uy = (p0y - (-1.55f)) / 2.5f;
    const float uz = (p0z - (-1.25f)) / 2.5f;
    const int ix = (int)floorf(ux * 64.0f);
    const int iy = (int)floorf(uy * 64.0f);
    const int iz = (int)floorf(uz * 64.0f);
    const bool inb = (ix >= 0) & (ix < 64) & (iy >= 0) & (iy < 64) & (iz >= 0) & (iz < 64);
    const int cx = min(max(ix, 0), 63);
    const int cy = min(max(iy, 0), 63);
    const int cz = min(max(iz, 0), 63);
    const bool occ = density[(cx * 64 + cy) * 64 + cz] > 0.5f;
    const bool mask = occ && inb;

    const int any_active = __syncthreads_or(mask ? 1 : 0);     // barrier 1
    if (!any_active) {
        if (t == 0) {
            out[ray * 3 + 0] = 1.0f;
            out[ray * 3 + 1] = 1.0f;
            out[ray * 3 + 2] = 1.0f;
        }
        return;
    }

    // ---- stage W2 hi/lo (int4 memcpy) + B' into h1 padding columns ----
    {
        const int4* src_hi = reinterpret_cast<const int4*>(gW2hi);
        const int4* src_lo = reinterpret_cast<const int4*>(gW2lo);
        int4* dst_hi = reinterpret_cast<int4*>(sW2hi);
        int4* dst_lo = reinterpret_cast<int4*>(sW2lo);
        #pragma unroll
        for (int i = t; i < (H * LDH) / 8; i += 128) {
            dst_hi[i] = src_hi[i];
            dst_lo[i] = src_lo[i];
        }
        // B' rows: one uint4 (8 halves) per row; threads 0-63 hi, 64-127 lo
        const int r = t & 63;
        const int4 v = (t < 64) ? reinterpret_cast<const int4*>(gBphi)[r]
                                : reinterpret_cast<const int4*>(gBplo)[r];
        __half* base = (t < 64) ? hH1hi : hH1lo;
        *reinterpret_cast<int4*>(base + r * LDH + 64) = v;
    }

    const unsigned wball = __ballot_sync(0xffffffffu, mask);
    const bool warp_active = (wball != 0u);

    const float zv = mask ? z : 0.0f;
    const float zj = zv + jitter[ray * S + t] * step;
    const float px = ox + zj * dx;
    const float py = oy + zj * dy;
    const float pz = oz + zj * dz;

    // ---- layer 1 (scalar fp32, K=3): float4 weight loads, 128-bit h1 stores ----
    if (warp_active) {
        uint4* hrowHi = reinterpret_cast<uint4*>(hH1hi + t * LDH);
        uint4* hrowLo = reinterpret_cast<uint4*>(hH1lo + t * LDH);
        #pragma unroll
        for (int j8 = 0; j8 < H; j8 += 8) {
            const float4 wx0 = *reinterpret_cast<const float4*>(W1 + j8);
            const float4 wx1 = *reinterpret_cast<const float4*>(W1 + j8 + 4);
            const float4 wy0 = *reinterpret_cast<const float4*>(W1 + H + j8);
            const float4 wy1 = *reinterpret_cast<const float4*>(W1 + H + j8 + 4);
            const float4 wz0 = *reinterpret_cast<const float4*>(W1 + 2 * H + j8);
            const float4 wz1 = *reinterpret_cast<const float4*>(W1 + 2 * H + j8 + 4);
            const float4 bb0 = *reinterpret_cast<const float4*>(b1 + j8);
            const float4 bb1 = *reinterpret_cast<const float4*>(b1 + j8 + 4);
            float vj[8];
            vj[0] = fmaxf(fmaf(px, wx0.x, fmaf(py, wy0.x, fmaf(pz, wz0.x, bb0.x))), 0.0f);
            vj[1] = fmaxf(fmaf(px, wx0.y, fmaf(py, wy0.y, fmaf(pz, wz0.y, bb0.y))), 0.0f);
            vj[2] = fmaxf(fmaf(px, wx0.z, fmaf(py, wy0.z, fmaf(pz, wz0.z, bb0.z))), 0.0f);
            vj[3] = fmaxf(fmaf(px, wx0.w, fmaf(py, wy0.w, fmaf(pz, wz0.w, bb0.w))), 0.0f);
            vj[4] = fmaxf(fmaf(px, wx1.x, fmaf(py, wy1.x, fmaf(pz, wz1.x, bb1.x))), 0.0f);
            vj[5] = fmaxf(fmaf(px, wx1.y, fmaf(py, wy1.y, fmaf(pz, wz1.y, bb1.y))), 0.0f);
            vj[6] = fmaxf(fmaf(px, wx1.z, fmaf(py, wy1.z, fmaf(pz, wz1.z, bb1.z))), 0.0f);
            vj[7] = fmaxf(fmaf(px, wx1.w, fmaf(py, wy1.w, fmaf(pz, wz1.w, bb1.w))), 0.0f);

            uint4 vhi, vlo;
            __half2* phi = reinterpret_cast<__half2*>(&vhi);
            __half2* plo = reinterpret_cast<__half2*>(&vlo);
            #pragma unroll
            for (int u = 0; u < 4; u++) {
                const float v0 = vj[2 * u], v1 = vj[2 * u + 1];
                const __half h0 = __float2half_rn(v0);
                const __half h1 = __float2half_rn(v1);
                phi[u] = __halves2half2(h0, h1);
                plo[u] = __halves2half2(__float2half_rn(v0 - __half2float(h0)),
                                        __float2half_rn(v1 - __half2float(h1)));
            }
            hrowHi[j8 >> 3] = vhi;
            hrowLo[j8 >> 3] = vlo;
        }
    }
    __syncthreads();   // barrier 2: h1 + W2 + B' staged

    const unsigned h1hiU = (unsigned)__cvta_generic_to_shared(hH1hi);
    const unsigned h1loU = (unsigned)__cvta_generic_to_shared(hH1lo);
    const unsigned w2hiU = (unsigned)__cvta_generic_to_shared(sW2hi);
    const unsigned w2loU = (unsigned)__cvta_generic_to_shared(sW2lo);

    const int g = lane >> 2;
    const int q = lane & 3;

    float hc[2][4];                       // heads C' (sigma,r | g,b logits)
    #pragma unroll
    for (int mt = 0; mt < 2; mt++)
        #pragma unroll
        for (int u = 0; u < 4; u++) hc[mt][u] = 0.0f;

    if (warp_active) {
        float C[2][8][4];                 // h2 accumulators, register-resident
        #pragma unroll
        for (int mt = 0; mt < 2; mt++)
            #pragma unroll
            for (int nt = 0; nt < 8; nt++)
                #pragma unroll
                for (int u = 0; u < 4; u++) C[mt][nt][u] = 0.0f;

        const int arow = lane & 15;
        const int acol = (lane >> 4) * 8;
        const int brow = lane & 15;

        #pragma unroll
        for (int k = 0; k < 4; k++) {
            unsigned aHi[2][4], aLo[2][4];
            #pragma unroll
            for (int mt = 0; mt < 2; mt++) {
                const unsigned off = (unsigned)(((warp * 32 + mt * 16 + arow) * LDH + k * 16 + acol) * 2);
                ldsm_x4(aHi[mt][0], aHi[mt][1], aHi[mt][2], aHi[mt][3], h1hiU + off);
                ldsm_x4(aLo[mt][0], aLo[mt][1], aLo[mt][2], aLo[mt][3], h1loU + off);
            }
            #pragma unroll
            for (int nt = 0; nt < 8; nt++) {
                const unsigned boff = (unsigned)(((k * 16 + brow) * LDH + nt * 8) * 2);
                unsigned bh0, bh1, bl0, bl1;
                ldsm_x2t(bh0, bh1, w2hiU + boff);
                ldsm_x2t(bl0, bl1, w2loU + boff);
                #pragma unroll
                for (int mt = 0; mt < 2; mt++) {
                    mma16816(C[mt][nt], aHi[mt][0], aHi[mt][1], aHi[mt][2], aHi[mt][3], bh0, bh1);
                    mma16816(C[mt][nt], aHi[mt][0], aHi[mt][1], aHi[mt][2], aHi[mt][3], bl0, bl1);
                    mma16816(C[mt][nt], aLo[mt][0], aLo[mt][1], aLo[mt][2], aLo[mt][3], bh0, bh1);
                }
            }
        }

        // ---- heads: relu(h2 + b2) @ [Wsig|Wrgb], A' packed from C in registers ----
        #pragma unroll
        for (int ntp = 0; ntp < 4; ntp++) {
            const unsigned bpoff = (unsigned)(((ntp * 16 + brow) * LDH + 64) * 2);
            unsigned bph0, bph1, bpl0, bpl1;
            ldsm_x2t(bph0, bph1, h1hiU + bpoff);
            ldsm_x2t(bpl0, bpl1, h1loU + bpoff);
            const float2 bb0 = *reinterpret_cast<const float2*>(b2 + (2 * ntp) * 8 + 2 * q);
            const float2 bb1 = *reinterpret_cast<const float2*>(b2 + (2 * ntp + 1) * 8 + 2 * q);
            #pragma unroll
            for (int mt = 0; mt < 2; mt++) {
                unsigned aH[4], aL[4];
                #pragma unroll
                for (int sub = 0; sub < 2; sub++) {
                    const float* c = C[mt][2 * ntp + sub];
                    const float2 bb = sub ? bb1 : bb0;
                    const float v0 = fmaxf(c[0] + bb.x, 0.0f);
                    const float v1 = fmaxf(c[1] + bb.y, 0.0f);
                    const float v2 = fmaxf(c[2] + bb.x, 0.0f);
                    const float v3 = fmaxf(c[3] + bb.y, 0.0f);
                    const __half2 h01 = __floats2half2_rn(v0, v1);
                    const __half2 h23 = __floats2half2_rn(v2, v3);
                    aH[2 * sub + 0] = h2u(h01);
                    aH[2 * sub + 1] = h2u(h23);
                    aL[2 * sub + 0] = h2u(__floats2half2_rn(v0 - __low2float(h01), v1 - __high2float(h01)));
                    aL[2 * sub + 1] = h2u(__floats2half2_rn(v2 - __low2float(h23), v3 - __high2float(h23)));
                }
                mma16816(hc[mt], aH[0], aH[1], aH[2], aH[3], bph0, bph1);
                mma16816(hc[mt], aH[0], aH[1], aH[2], aH[3], bpl0, bpl1);
                mma16816(hc[mt], aL[0], aL[1], aL[2], aL[3], bph0, bph1);
            }
        }
    }

    // ---- intra-warp redistribution of head logits (no smem, no barrier) ----
    // Target thread (sample row = lane) pulls its (sigma,r,g,b) from the
    // fragment owners: source lane = (lane&7)*4 + q', value index by (mt,half).
    const int mt_t   = lane >> 4;
    const int half_t = (lane >> 3) & 1;
    const int src0   = (lane & 7) * 4;
    float sigL = 0.0f, crL = 0.0f, cgL = 0.0f, cbL = 0.0f;
    #pragma unroll
    for (int mt = 0; mt < 2; mt++) {
        #pragma unroll
        for (int hf = 0; hf < 2; hf++) {
            const float v00 = __shfl_sync(0xffffffffu, hc[mt][hf * 2 + 0], src0);
            const float v01 = __shfl_sync(0xffffffffu, hc[mt][hf * 2 + 1], src0);
            const float v10 = __shfl_sync(0xffffffffu, hc[mt][hf * 2 + 0], src0 + 1);
            const float v11 = __shfl_sync(0xffffffffu, hc[mt][hf * 2 + 1], src0 + 1);
            if (mt == mt_t && hf == half_t) { sigL = v00; crL = v01; cgL = v10; cbL = v11; }
        }
    }

    // ---- per-sample nonlinearities ----
    float alpha = 0.0f, r = 0.0f, gg = 0.0f, b = 0.0f;
    if (mask) {
        const float sigma = sigL + bsig[0];
        const float tau = fmaxf(sigma, 0.0f) * step;
        alpha = 1.0f - __expf(-tau);
        r  = 1.0f / (1.0f + __expf(-(crL + brgb[0])));
        gg = 1.0f / (1.0f + __expf(-(cgL + brgb[1])));
        b  = 1.0f / (1.0f + __expf(-(cbL + brgb[2])));
    }

    // ---- composite: warp scan; pre-factors applied at combine (1 barrier) ----
    const float f = 1.0f - alpha + 1e-10f;
    float incl = f;
    #pragma unroll
    for (int off = 1; off < 32; off <<= 1) {
        const float v = __shfl_up_sync(0xffffffffu, incl, off);
        if (lane >= off) incl *= v;
    }
    const float wtot = __shfl_sync(0xffffffffu, incl, 31);
    float excl = __shfl_up_sync(0xffffffffu, incl, 1);
    if (lane == 0) excl = 1.0f;

    const float w = alpha * excl;    // NOTE: warp-prefix `pre` applied at combine
    float wr = w * r, wg = w * gg, wb = w * b;
    #pragma unroll
    for (int off = 16; off > 0; off >>= 1) {
        wr += __shfl_down_sync(0xffffffffu, wr, off);
        wg += __shfl_down_sync(0xffffffffu, wg, off);
        wb += __shfl_down_sync(0xffffffffu, wb, off);
    }
    if (lane == 0) {
        sWprod[warp] = wtot;
        sSum[warp * 3 + 0] = wr;
        sSum[warp * 3 + 1] = wg;
        sSum[warp * 3 + 2] = wb;
    }
    __syncthreads();   // barrier 3

    if (t == 0) {
        const float p1 = sWprod[0];
        const float p2 = p1 * sWprod[1];
        const float p3 = p2 * sWprod[2];
        const float no_hit = p3 * sWprod[3];
        out[ray * 3 + 0] = no_hit + sSum[0] + p1 * sSum[3] + p2 * sSum[6] + p3 * sSum[9];
        out[ray * 3 + 1] = no_hit + sSum[1] + p1 * sSum[4] + p2 * sSum[7] + p3 * sSum[10];
        out[ray * 3 + 2] = no_hit + sSum[2] + p1 * sSum[5] + p2 * sSum[8] + p3 * sSum[11];
    }
}

extern "C" void kernel_launch(void* const* d_in, const int* in_sizes, int n_in,
                              void* d_out, int out_size)
{
    const float* rays_o  = (const float*)d_in[0];
    const float* rays_d  = (const float*)d_in[1];
    const float* nearv   = (const float*)d_in[2];
    const float* farv    = (const float*)d_in[3];
    const float* jitter  = (const float*)d_in[4];
    const float* density = (const float*)d_in[5];
    const float* W1      = (const float*)d_in[6];
    const float* b1      = (const float*)d_in[7];
    const float* W2      = (const float*)d_in[8];
    const float* b2      = (const float*)d_in[9];
    const float* Wsig    = (const float*)d_in[10];
    const float* bsig    = (const float*)d_in[11];
    const float* Wrgb    = (const float*)d_in[12];
    const float* brgb    = (const float*)d_in[13];

    const int n_rays = in_sizes[2];   // near has one entry per ray

    cudaFuncSetAttribute(render_kernel, cudaFuncAttributeMaxDynamicSharedMemorySize, SMEM_BYTES);

    pack_kernel<<<(H * H + 127) / 128, 128>>>(W2, Wsig, Wrgb);
    render_kernel<<<n_rays, 128, SMEM_BYTES>>>(rays_o, rays_d, nearv, farv, jitter, density,
                                               W1, b1, b2, bsig, brgb,
                                               (float*)d_out);
}

// round 13
// speedup vs baseline: 1.6021x; 1.1420x over previous
#include <cuda_runtime.h>
#include <cuda_fp16.h>
#include <cstring>

#define S 128
#define H 64
#define LDH 72     // leading dim (halves) for h1 tiles; 144 B = 9*16B granules -> ldmatrix conflict-free

// Dynamic shared memory layout (bytes):
//   [0, 18432)      h1_hi half[128*LDH]
//   [18432, 36864)  h1_lo half[128*LDH]
//   [36864, 36880)  sWprod float[4]
//   [36880, 36928)  sSum  float[4][3]
#define SMEM_BYTES 36928

// W2 / heads-B' pre-packed DIRECTLY in mma.m16n8k16 B-fragment register layout.
// Index: [kt*8+nt][lane] (uint2 = {b0,b1}), lane q=lane&3,g=lane>>2:
//   b0 = {B[kt*16+2q][nt*8+g], B[kt*16+2q+1][nt*8+g]}, b1 = rows +8.
__device__ __align__(16) uint2 gFW2hi[4 * 8 * 32];   // 8 KB
__device__ __align__(16) uint2 gFW2lo[4 * 8 * 32];
__device__ __align__(16) uint2 gFBphi[4 * 32];       // heads B' = [Wsig|Wrgb|0...], N=8
__device__ __align__(16) uint2 gFBplo[4 * 32];

__device__ __forceinline__ unsigned pack2(float a, float b, bool lo) {
    const __half ha = __float2half_rn(a);
    const __half hb = __float2half_rn(b);
    __half2 h;
    if (!lo) h = __halves2half2(ha, hb);
    else     h = __halves2half2(__float2half_rn(a - __half2float(ha)),
                                __float2half_rn(b - __half2float(hb)));
    unsigned u; memcpy(&u, &h, 4); return u;
}

__global__ void pack_kernel(const float* __restrict__ W2,
                            const float* __restrict__ Wsig,
                            const float* __restrict__ Wrgb)
{
    const int i = blockIdx.x * blockDim.x + threadIdx.x;
    if (i < 4 * 8 * 32) {
        const int lane = i & 31, nt = (i >> 5) & 7, kt = i >> 8;
        const int q = lane & 3, g = lane >> 2;
        const int k0 = kt * 16 + 2 * q;
        const int j  = nt * 8 + g;
        const float w00 = W2[(k0 + 0) * H + j];
        const float w01 = W2[(k0 + 1) * H + j];
        const float w10 = W2[(k0 + 8) * H + j];
        const float w11 = W2[(k0 + 9) * H + j];
        gFW2hi[i] = make_uint2(pack2(w00, w01, false), pack2(w10, w11, false));
        gFW2lo[i] = make_uint2(pack2(w00, w01, true),  pack2(w10, w11, true));
    }
    if (i < 4 * 32) {
        const int lane = i & 31, ntp = i >> 5;
        const int q = lane & 3, g = lane >> 2;
        const int k0 = ntp * 16 + 2 * q;
        // B'[k][n]: n0 = Wsig[k], n1..3 = Wrgb[k*3 + n-1], n4..7 = 0
        auto bp = [&](int k, int n) -> float {
            if (n == 0) return Wsig[k];
            if (n <= 3) return Wrgb[k * 3 + (n - 1)];
            return 0.0f;
        };
        const float w00 = bp(k0 + 0, g), w01 = bp(k0 + 1, g);
        const float w10 = bp(k0 + 8, g), w11 = bp(k0 + 9, g);
        gFBphi[i] = make_uint2(pack2(w00, w01, false), pack2(w10, w11, false));
        gFBplo[i] = make_uint2(pack2(w00, w01, true),  pack2(w10, w11, true));
    }
}

__device__ __forceinline__ void ldsm_x4(unsigned& r0, unsigned& r1, unsigned& r2, unsigned& r3, unsigned a) {
    asm volatile("ldmatrix.sync.aligned.m8n8.x4.shared.b16 {%0,%1,%2,%3}, [%4];"
                 : "=r"(r0), "=r"(r1), "=r"(r2), "=r"(r3) : "r"(a));
}
__device__ __forceinline__ void mma16816(float* d, unsigned a0, unsigned a1, unsigned a2, unsigned a3,
                                         unsigned b0, unsigned b1) {
    asm volatile("mma.sync.aligned.m16n8k16.row.col.f32.f16.f16.f32 "
                 "{%0,%1,%2,%3},{%4,%5,%6,%7},{%8,%9},{%0,%1,%2,%3};"
                 : "+f"(d[0]), "+f"(d[1]), "+f"(d[2]), "+f"(d[3])
                 : "r"(a0), "r"(a1), "r"(a2), "r"(a3), "r"(b0), "r"(b1));
}
__device__ __forceinline__ unsigned h2u(__half2 h) { unsigned u; memcpy(&u, &h, 4); return u; }

__global__ __launch_bounds__(128, 4)
void render_kernel(const float* __restrict__ rays_o,
                   const float* __restrict__ rays_d,
                   const float* __restrict__ nearv,
                   const float* __restrict__ farv,
                   const float* __restrict__ jitter,
                   const float* __restrict__ density,
                   const float* __restrict__ W1,
                   const float* __restrict__ b1,
                   const float* __restrict__ b2,
                   const float* __restrict__ bsig,
                   const float* __restrict__ brgb,
                   float* __restrict__ out)
{
    extern __shared__ __align__(16) char smem[];
    __half* hH1hi = reinterpret_cast<__half*>(smem);
    __half* hH1lo = reinterpret_cast<__half*>(smem + 18432);
    float*  sWprod = reinterpret_cast<float*>(smem + 36864);   // [4]
    float*  sSum   = reinterpret_cast<float*>(smem + 36880);   // [4][3]

    const int t    = threadIdx.x;     // 0..127, sample index
    const int lane = t & 31;
    const int warp = t >> 5;          // 0..3
    const int ray  = blockIdx.x;

    // ---- per-sample ray setup + occupancy-grid mask ----
    const float ox = rays_o[ray * 3 + 0];
    const float oy = rays_o[ray * 3 + 1];
    const float oz = rays_o[ray * 3 + 2];
    const float dx = rays_d[ray * 3 + 0];
    const float dy = rays_d[ray * 3 + 1];
    const float dz = rays_d[ray * 3 + 2];
    const float nr = nearv[ray];
    const float fr = farv[ray];
    const float step = (fr - nr) * (1.0f / (float)S);
    const float z = nr + (float)t * step;

    const float p0x = ox + z * dx;
    const float p0y = oy + z * dy;
    const float p0z = oz + z * dz;
    const float ux = (p0x - (-1.25f)) / 2.5f;
    const float uy = (p0y - (-1.55f)) / 2.5f;
    const float uz = (p0z - (-1.25f)) / 2.5f;
    const int ix = (int)floorf(ux * 64.0f);
    const int iy = (int)floorf(uy * 64.0f);
    const int iz = (int)floorf(uz * 64.0f);
    const bool inb = (ix >= 0) & (ix < 64) & (iy >= 0) & (iy < 64) & (iz >= 0) & (iz < 64);
    const int cx = min(max(ix, 0), 63);
    const int cy = min(max(iy, 0), 63);
    const int cz = min(max(iz, 0), 63);
    const bool occ = density[(cx * 64 + cy) * 64 + cz] > 0.5f;
    const bool mask = occ && inb;

    const int any_active = __syncthreads_or(mask ? 1 : 0);     // barrier 1
    if (!any_active) {
        if (t == 0) {
            out[ray * 3 + 0] = 1.0f;
            out[ray * 3 + 1] = 1.0f;
            out[ray * 3 + 2] = 1.0f;
        }
        return;
    }

    const unsigned wball = __ballot_sync(0xffffffffu, mask);
    const bool warp_active = (wball != 0u);

    const float zv = mask ? z : 0.0f;
    const float zj = zv + jitter[ray * S + t] * step;
    const float px = ox + zj * dx;
    const float py = oy + zj * dy;
    const float pz = oz + zj * dz;

    // ---- layer 1 (scalar fp32, K=3): float4 weight loads, 128-bit h1 stores ----
    if (warp_active) {
        uint4* hrowHi = reinterpret_cast<uint4*>(hH1hi + t * LDH);
        uint4* hrowLo = reinterpret_cast<uint4*>(hH1lo + t * LDH);
        #pragma unroll
        for (int j8 = 0; j8 < H; j8 += 8) {
            const float4 wx0 = *reinterpret_cast<const float4*>(W1 + j8);
            const float4 wx1 = *reinterpret_cast<const float4*>(W1 + j8 + 4);
            const float4 wy0 = *reinterpret_cast<const float4*>(W1 + H + j8);
            const float4 wy1 = *reinterpret_cast<const float4*>(W1 + H + j8 + 4);
            const float4 wz0 = *reinterpret_cast<const float4*>(W1 + 2 * H + j8);
            const float4 wz1 = *reinterpret_cast<const float4*>(W1 + 2 * H + j8 + 4);
            const float4 bb0 = *reinterpret_cast<const float4*>(b1 + j8);
            const float4 bb1 = *reinterpret_cast<const float4*>(b1 + j8 + 4);
            float vj[8];
            vj[0] = fmaxf(fmaf(px, wx0.x, fmaf(py, wy0.x, fmaf(pz, wz0.x, bb0.x))), 0.0f);
            vj[1] = fmaxf(fmaf(px, wx0.y, fmaf(py, wy0.y, fmaf(pz, wz0.y, bb0.y))), 0.0f);
            vj[2] = fmaxf(fmaf(px, wx0.z, fmaf(py, wy0.z, fmaf(pz, wz0.z, bb0.z))), 0.0f);
            vj[3] = fmaxf(fmaf(px, wx0.w, fmaf(py, wy0.w, fmaf(pz, wz0.w, bb0.w))), 0.0f);
            vj[4] = fmaxf(fmaf(px, wx1.x, fmaf(py, wy1.x, fmaf(pz, wz1.x, bb1.x))), 0.0f);
            vj[5] = fmaxf(fmaf(px, wx1.y, fmaf(py, wy1.y, fmaf(pz, wz1.y, bb1.y))), 0.0f);
            vj[6] = fmaxf(fmaf(px, wx1.z, fmaf(py, wy1.z, fmaf(pz, wz1.z, bb1.z))), 0.0f);
            vj[7] = fmaxf(fmaf(px, wx1.w, fmaf(py, wy1.w, fmaf(pz, wz1.w, bb1.w))), 0.0f);

            uint4 vhi, vlo;
            __half2* phi = reinterpret_cast<__half2*>(&vhi);
            __half2* plo = reinterpret_cast<__half2*>(&vlo);
            #pragma unroll
            for (int u = 0; u < 4; u++) {
                const float v0 = vj[2 * u], v1 = vj[2 * u + 1];
                const __half h0 = __float2half_rn(v0);
                const __half h1 = __float2half_rn(v1);
                phi[u] = __halves2half2(h0, h1);
                plo[u] = __halves2half2(__float2half_rn(v0 - __half2float(h0)),
                                        __float2half_rn(v1 - __half2float(h1)));
            }
            hrowHi[j8 >> 3] = vhi;
            hrowLo[j8 >> 3] = vlo;
        }
    }
    __syncthreads();   // barrier 2: h1 staged

    const unsigned h1hiU = (unsigned)__cvta_generic_to_shared(hH1hi);
    const unsigned h1loU = (unsigned)__cvta_generic_to_shared(hH1lo);

    const int q = lane & 3;

    float hc[2][4];                       // heads C' (sigma,r | g,b logits)
    #pragma unroll
    for (int mt = 0; mt < 2; mt++)
        #pragma unroll
        for (int u = 0; u < 4; u++) hc[mt][u] = 0.0f;

    if (warp_active) {
        float C[2][8][4];                 // h2 accumulators, register-resident
        #pragma unroll
        for (int mt = 0; mt < 2; mt++)
            #pragma unroll
            for (int nt = 0; nt < 8; nt++)
                #pragma unroll
                for (int u = 0; u < 4; u++) C[mt][nt][u] = 0.0f;

        const int arow = lane & 15;
        const int acol = (lane >> 4) * 8;

        #pragma unroll
        for (int k = 0; k < 4; k++) {
            unsigned aHi[2][4], aLo[2][4];
            #pragma unroll
            for (int mt = 0; mt < 2; mt++) {
                const unsigned off = (unsigned)(((warp * 32 + mt * 16 + arow) * LDH + k * 16 + acol) * 2);
                ldsm_x4(aHi[mt][0], aHi[mt][1], aHi[mt][2], aHi[mt][3], h1hiU + off);
                ldsm_x4(aLo[mt][0], aLo[mt][1], aLo[mt][2], aLo[mt][3], h1loU + off);
            }
            #pragma unroll
            for (int nt = 0; nt < 8; nt++) {
                // B fragments: coalesced 8-byte loads from pre-packed global (L1-hot)
                const uint2 bh = gFW2hi[(k * 8 + nt) * 32 + lane];
                const uint2 bl = gFW2lo[(k * 8 + nt) * 32 + lane];
                #pragma unroll
                for (int mt = 0; mt < 2; mt++) {
                    mma16816(C[mt][nt], aHi[mt][0], aHi[mt][1], aHi[mt][2], aHi[mt][3], bh.x, bh.y);
                    mma16816(C[mt][nt], aHi[mt][0], aHi[mt][1], aHi[mt][2], aHi[mt][3], bl.x, bl.y);
                    mma16816(C[mt][nt], aLo[mt][0], aLo[mt][1], aLo[mt][2], aLo[mt][3], bh.x, bh.y);
                }
            }
        }

        // ---- heads: relu(h2 + b2) @ [Wsig|Wrgb], A' packed from C in registers ----
        #pragma unroll
        for (int ntp = 0; ntp < 4; ntp++) {
            const uint2 bph = gFBphi[ntp * 32 + lane];
            const uint2 bpl = gFBplo[ntp * 32 + lane];
            const float2 bb0 = *reinterpret_cast<const float2*>(b2 + (2 * ntp) * 8 + 2 * q);
            const float2 bb1 = *reinterpret_cast<const float2*>(b2 + (2 * ntp + 1) * 8 + 2 * q);
            #pragma unroll
            for (int mt = 0; mt < 2; mt++) {
                unsigned aH[4], aL[4];
                #pragma unroll
                for (int sub = 0; sub < 2; sub++) {
                    const float* c = C[mt][2 * ntp + sub];
                    const float2 bb = sub ? bb1 : bb0;
                    const float v0 = fmaxf(c[0] + bb.x, 0.0f);
                    const float v1 = fmaxf(c[1] + bb.y, 0.0f);
                    const float v2 = fmaxf(c[2] + bb.x, 0.0f);
                    const float v3 = fmaxf(c[3] + bb.y, 0.0f);
                    const __half2 h01 = __floats2half2_rn(v0, v1);
                    const __half2 h23 = __floats2half2_rn(v2, v3);
                    aH[2 * sub + 0] = h2u(h01);
                    aH[2 * sub + 1] = h2u(h23);
                    aL[2 * sub + 0] = h2u(__floats2half2_rn(v0 - __low2float(h01), v1 - __high2float(h01)));
                    aL[2 * sub + 1] = h2u(__floats2half2_rn(v2 - __low2float(h23), v3 - __high2float(h23)));
                }
                mma16816(hc[mt], aH[0], aH[1], aH[2], aH[3], bph.x, bph.y);
                mma16816(hc[mt], aH[0], aH[1], aH[2], aH[3], bpl.x, bpl.y);
                mma16816(hc[mt], aL[0], aL[1], aL[2], aL[3], bph.x, bph.y);
            }
        }
    }

    // ---- intra-warp redistribution of head logits (no smem, no barrier) ----
    const int mt_t   = lane >> 4;
    const int half_t = (lane >> 3) & 1;
    const int src0   = (lane & 7) * 4;
    float sigL = 0.0f, crL = 0.0f, cgL = 0.0f, cbL = 0.0f;
    #pragma unroll
    for (int mt = 0; mt < 2; mt++) {
        #pragma unroll
        for (int hf = 0; hf < 2; hf++) {
            const float v00 = __shfl_sync(0xffffffffu, hc[mt][hf * 2 + 0], src0);
            const float v01 = __shfl_sync(0xffffffffu, hc[mt][hf * 2 + 1], src0);
            const float v10 = __shfl_sync(0xffffffffu, hc[mt][hf * 2 + 0], src0 + 1);
            const float v11 = __shfl_sync(0xffffffffu, hc[mt][hf * 2 + 1], src0 + 1);
            if (mt == mt_t && hf == half_t) { sigL = v00; crL = v01; cgL = v10; cbL = v11; }
        }
    }

    // ---- per-sample nonlinearities ----
    float alpha = 0.0f, r = 0.0f, gg = 0.0f, b = 0.0f;
    if (mask) {
        const float sigma = sigL + bsig[0];
        const float tau = fmaxf(sigma, 0.0f) * step;
        alpha = 1.0f - __expf(-tau);
        r  = 1.0f / (1.0f + __expf(-(crL + brgb[0])));
        gg = 1.0f / (1.0f + __expf(-(cgL + brgb[1])));
        b  = 1.0f / (1.0f + __expf(-(cbL + brgb[2])));
    }

    // ---- composite: warp scan; pre-factors applied at combine (1 barrier) ----
    const float f = 1.0f - alpha + 1e-10f;
    float incl = f;
    #pragma unroll
    for (int off = 1; off < 32; off <<= 1) {
        const float v = __shfl_up_sync(0xffffffffu, incl, off);
        if (lane >= off) incl *= v;
    }
    const float wtot = __shfl_sync(0xffffffffu, incl, 31);
    float excl = __shfl_up_sync(0xffffffffu, incl, 1);
    if (lane == 0) excl = 1.0f;

    const float w = alpha * excl;    // warp-prefix `pre` applied at combine
    float wr = w * r, wg = w * gg, wb = w * b;
    #pragma unroll
    for (int off = 16; off > 0; off >>= 1) {
        wr += __shfl_down_sync(0xffffffffu, wr, off);
        wg += __shfl_down_sync(0xffffffffu, wg, off);
        wb += __shfl_down_sync(0xffffffffu, wb, off);
    }
    if (lane == 0) {
        sWprod[warp] = wtot;
        sSum[warp * 3 + 0] = wr;
        sSum[warp * 3 + 1] = wg;
        sSum[warp * 3 + 2] = wb;
    }
    __syncthreads();   // barrier 3

    if (t == 0) {
        const float p1 = sWprod[0];
        const float p2 = p1 * sWprod[1];
        const float p3 = p2 * sWprod[2];
        const float no_hit = p3 * sWprod[3];
        out[ray * 3 + 0] = no_hit + sSum[0] + p1 * sSum[3] + p2 * sSum[6] + p3 * sSum[9];
        out[ray * 3 + 1] = no_hit + sSum[1] + p1 * sSum[4] + p2 * sSum[7] + p3 * sSum[10];
        out[ray * 3 + 2] = no_hit + sSum[2] + p1 * sSum[5] + p2 * sSum[8] + p3 * sSum[11];
    }
}

extern "C" void kernel_launch(void* const* d_in, const int* in_sizes, int n_in,
                              void* d_out, int out_size)
{
    const float* rays_o  = (const float*)d_in[0];
    const float* rays_d  = (const float*)d_in[1];
    const float* nearv   = (const float*)d_in[2];
    const float* farv    = (const float*)d_in[3];
    const float* jitter  = (const float*)d_in[4];
    const float* density = (const float*)d_in[5];
    const float* W1      = (const float*)d_in[6];
    const float* b1      = (const float*)d_in[7];
    const float* W2      = (const float*)d_in[8];
    const float* b2      = (const float*)d_in[9];
    const float* Wsig    = (const float*)d_in[10];
    const float* bsig    = (const float*)d_in[11];
    const float* Wrgb    = (const float*)d_in[12];
    const float* brgb    = (const float*)d_in[13];

    const int n_rays = in_sizes[2];   // near has one entry per ray

    cudaFuncSetAttribute(render_kernel, cudaFuncAttributeMaxDynamicSharedMemorySize, SMEM_BYTES);

    pack_kernel<<<8, 128>>>(W2, Wsig, Wrgb);
    render_kernel<<<n_rays, 128, SMEM_BYTES>>>(rays_o, rays_d, nearv, farv, jitter, density,
                                               W1, b1, b2, bsig, brgb,
                                               (float*)d_out);
}